// round 11
// baseline (speedup 1.0000x reference)
#include <cuda_runtime.h>
#include <cuda_bf16.h>
#include <cstddef>

#define Bz 32
#define Nn 4096
#define Dd 256
#define Kk 8

// ---------------- scratch (device globals; no allocations allowed) ----------
__device__ float g_keys[(size_t)Bz * Nn * Dd];
__device__ float g_vals[(size_t)Bz * Nn * Dd];
__device__ float g_mean[Bz * Nn];
__device__ float g_rstd[Bz * Nn];
__device__ float g_slots[Bz * Kk * Dd];
__device__ float g_q[Bz * Kk * Dd];
__device__ float g_upd[Bz * Kk * Dd];
__device__ float g_attn[(size_t)Bz * Kk * Nn];
__device__ float g_rowsum[Bz * Kk];

__device__ __forceinline__ void wred2(float& a, float& b) {
#pragma unroll
    for (int o = 16; o > 0; o >>= 1) {
        a += __shfl_xor_sync(0xffffffffu, a, o);
        b += __shfl_xor_sync(0xffffffffu, b, o);
    }
}

// ---------------- slot init: mu + exp(logsigma) * noise ---------------------
__global__ void k_init_slots(const float* __restrict__ noise,
                             const float* __restrict__ mu,
                             const float* __restrict__ ls) {
    int i = blockIdx.x * 256 + threadIdx.x;
    int d = i & 255;
    g_slots[i] = mu[d] + expf(ls[d]) * noise[i];
}

// ---------------- per-row LN stats of embeddings (warp per row) -------------
__global__ void __launch_bounds__(256) k_rowstats(const float* __restrict__ emb) {
    int row = blockIdx.x * 8 + (threadIdx.x >> 5);
    int lane = threadIdx.x & 31;
    const float4* er = (const float4*)(emb + (size_t)row * 256);
    float4 v1 = er[lane];
    float4 v2 = er[lane + 32];
    float s = v1.x + v1.y + v1.z + v1.w + v2.x + v2.y + v2.z + v2.w;
    float ss = v1.x * v1.x + v1.y * v1.y + v1.z * v1.z + v1.w * v1.w
             + v2.x * v2.x + v2.y * v2.y + v2.z * v2.z + v2.w * v2.w;
    wred2(s, ss);
    if (lane == 0) {
        float m = s * (1.f / 256.f);
        float var = ss * (1.f / 256.f) - m * m;
        g_mean[row] = m;
        g_rstd[row] = rsqrtf(var + 1e-5f);
    }
}

// ---------------- dual GEMM: keys/values = LN(emb) @ Wk^T / Wv^T ------------
// M = B*N = 131072, K = 256, N = 256. Tiles 64x64x16, 4x4 micro-tiles.
__global__ void __launch_bounds__(256) k_dualgemm(const float* __restrict__ emb,
                                                  const float* __restrict__ Wk,
                                                  const float* __restrict__ Wv,
                                                  const float* __restrict__ lg,
                                                  const float* __restrict__ lb) {
    __shared__ float As[16][64];
    __shared__ float Bk[16][64];
    __shared__ float Bv[16][64];

    int m0 = blockIdx.x * 64;
    int d0 = blockIdx.y * 64;
    int tid = threadIdx.x;
    int tx = tid & 15, ty = tid >> 4;
    int lrow = tid >> 2, lc4 = tid & 3;

    // LN params for the row this thread loads (fixed across k-loop)
    float mrow = g_mean[m0 + lrow];
    float rrow = g_rstd[m0 + lrow];

    float ck[4][4] = {}, cv[4][4] = {};

    for (int k0 = 0; k0 < 256; k0 += 16) {
        int c = k0 + lc4 * 4;
        float4 e = *(const float4*)(emb + (size_t)(m0 + lrow) * 256 + c);
        float4 gg = *(const float4*)(lg + c);
        float4 bb = *(const float4*)(lb + c);
        float4 a;
        a.x = (e.x - mrow) * rrow * gg.x + bb.x;
        a.y = (e.y - mrow) * rrow * gg.y + bb.y;
        a.z = (e.z - mrow) * rrow * gg.z + bb.z;
        a.w = (e.w - mrow) * rrow * gg.w + bb.w;
        float4 bk = *(const float4*)(Wk + (size_t)(d0 + lrow) * 256 + c);
        float4 bv = *(const float4*)(Wv + (size_t)(d0 + lrow) * 256 + c);

        As[lc4 * 4 + 0][lrow] = a.x;  As[lc4 * 4 + 1][lrow] = a.y;
        As[lc4 * 4 + 2][lrow] = a.z;  As[lc4 * 4 + 3][lrow] = a.w;
        Bk[lc4 * 4 + 0][lrow] = bk.x; Bk[lc4 * 4 + 1][lrow] = bk.y;
        Bk[lc4 * 4 + 2][lrow] = bk.z; Bk[lc4 * 4 + 3][lrow] = bk.w;
        Bv[lc4 * 4 + 0][lrow] = bv.x; Bv[lc4 * 4 + 1][lrow] = bv.y;
        Bv[lc4 * 4 + 2][lrow] = bv.z; Bv[lc4 * 4 + 3][lrow] = bv.w;
        __syncthreads();

#pragma unroll
        for (int kk = 0; kk < 16; kk++) {
            float4 a4 = *(float4*)&As[kk][ty * 4];
            float4 k4 = *(float4*)&Bk[kk][tx * 4];
            float4 v4 = *(float4*)&Bv[kk][tx * 4];
            float av[4] = {a4.x, a4.y, a4.z, a4.w};
            float kv[4] = {k4.x, k4.y, k4.z, k4.w};
            float vv[4] = {v4.x, v4.y, v4.z, v4.w};
#pragma unroll
            for (int i = 0; i < 4; i++)
#pragma unroll
                for (int j = 0; j < 4; j++) {
                    ck[i][j] += av[i] * kv[j];
                    cv[i][j] += av[i] * vv[j];
                }
        }
        __syncthreads();
    }

#pragma unroll
    for (int i = 0; i < 4; i++) {
        size_t ro = (size_t)(m0 + ty * 4 + i) * 256 + d0 + tx * 4;
        *(float4*)(g_keys + ro) = make_float4(ck[i][0], ck[i][1], ck[i][2], ck[i][3]);
        *(float4*)(g_vals + ro) = make_float4(cv[i][0], cv[i][1], cv[i][2], cv[i][3]);
    }
}

// ---------------- slots LN + queries (block per batch) ----------------------
__global__ void __launch_bounds__(256) k_slots_q(const float* __restrict__ lg,
                                                 const float* __restrict__ lb,
                                                 const float* __restrict__ Wq) {
    int b = blockIdx.x, tid = threadIdx.x;
    if (b == 0) g_rowsum[tid] = 0.f;  // zero rowsums for this iteration
    __shared__ float sn[8][256];
    int w = tid >> 5, lane = tid & 31;
    {
        const float* sr = g_slots + (b * 8 + w) * 256;
        float4 v1 = *(const float4*)(sr + lane * 4);
        float4 v2 = *(const float4*)(sr + 128 + lane * 4);
        float s = v1.x + v1.y + v1.z + v1.w + v2.x + v2.y + v2.z + v2.w;
        float ss = v1.x * v1.x + v1.y * v1.y + v1.z * v1.z + v1.w * v1.w
                 + v2.x * v2.x + v2.y * v2.y + v2.z * v2.z + v2.w * v2.w;
        wred2(s, ss);
        float m = s * (1.f / 256.f);
        float var = ss * (1.f / 256.f) - m * m;
        float rs = rsqrtf(var + 1e-5f);
        int d = lane * 4;
        sn[w][d + 0] = (v1.x - m) * rs * lg[d + 0] + lb[d + 0];
        sn[w][d + 1] = (v1.y - m) * rs * lg[d + 1] + lb[d + 1];
        sn[w][d + 2] = (v1.z - m) * rs * lg[d + 2] + lb[d + 2];
        sn[w][d + 3] = (v1.w - m) * rs * lg[d + 3] + lb[d + 3];
        int d2 = d + 128;
        sn[w][d2 + 0] = (v2.x - m) * rs * lg[d2 + 0] + lb[d2 + 0];
        sn[w][d2 + 1] = (v2.y - m) * rs * lg[d2 + 1] + lb[d2 + 1];
        sn[w][d2 + 2] = (v2.z - m) * rs * lg[d2 + 2] + lb[d2 + 2];
        sn[w][d2 + 3] = (v2.w - m) * rs * lg[d2 + 3] + lb[d2 + 3];
    }
    __syncthreads();

    int j = tid;
    float acc[8] = {};
    const float4* wr = (const float4*)(Wq + (size_t)j * 256);
#pragma unroll 4
    for (int c4 = 0; c4 < 64; c4++) {
        float4 wv = wr[c4];
#pragma unroll
        for (int r = 0; r < 8; r++) {
            float4 sv = *(float4*)&sn[r][c4 * 4];
            acc[r] += wv.x * sv.x + wv.y * sv.y + wv.z * sv.z + wv.w * sv.w;
        }
    }
#pragma unroll
    for (int r = 0; r < 8; r++) g_q[(b * 8 + r) * 256 + j] = acc[r];
}

// ---------------- dots + softmax over slots + EPS + rowsum ------------------
__global__ void __launch_bounds__(256) k_dots(float* __restrict__ attn) {
    __shared__ float qs[8][260];   // pad 260: kills same-bank across k rows
    __shared__ float ks[32][260];
    __shared__ float ds[32][8];
    int b = blockIdx.y, n0 = blockIdx.x * 32, tid = threadIdx.x;

    const float4* qsrc = (const float4*)(g_q + b * 8 * 256);
#pragma unroll
    for (int i = 0; i < 2; i++) {
        int p = tid + i * 256; int r = p >> 6, c4 = p & 63;
        *(float4*)&qs[r][c4 * 4] = qsrc[p];
    }
    const float4* ksrc = (const float4*)(g_keys + ((size_t)b * 4096 + n0) * 256);
#pragma unroll
    for (int i = 0; i < 8; i++) {
        int p = tid + i * 256; int r = p >> 6, c4 = p & 63;
        *(float4*)&ks[r][c4 * 4] = ksrc[p];
    }
    __syncthreads();

    int k = tid & 7, nl = tid >> 3;
    float acc = 0.f;
#pragma unroll 8
    for (int c4 = 0; c4 < 64; c4++) {
        float4 a = *(float4*)&qs[k][c4 * 4];
        float4 c = *(float4*)&ks[nl][c4 * 4];
        acc += a.x * c.x + a.y * c.y + a.z * c.z + a.w * c.w;
    }
    ds[nl][k] = acc * 0.0625f;  // SCALE = 256^-0.5
    __syncthreads();

    if (tid < 32) {
        float mx = -1e30f;
#pragma unroll
        for (int kk = 0; kk < 8; kk++) mx = fmaxf(mx, ds[tid][kk]);
        float e[8]; float s = 0.f;
#pragma unroll
        for (int kk = 0; kk < 8; kk++) { e[kk] = expf(ds[tid][kk] - mx); s += e[kk]; }
        float inv = 1.f / s;
#pragma unroll
        for (int kk = 0; kk < 8; kk++) {
            float a = e[kk] * inv + 1e-8f;
            ds[tid][kk] = a;
            attn[(size_t)(b * 8 + kk) * 4096 + n0 + tid] = a;
        }
    }
    __syncthreads();
    if (tid < 8) {
        float s = 0.f;
#pragma unroll
        for (int nn = 0; nn < 32; nn++) s += ds[nn][tid];
        atomicAdd(&g_rowsum[b * 8 + tid], s);
    }
}

// ---------------- updates = (values^T @ attn) / rowsum ----------------------
__global__ void __launch_bounds__(256) k_updates(const float* __restrict__ attn) {
    __shared__ float vs[64][32];
    __shared__ float as_[8][64];
    int b = blockIdx.y, d0 = blockIdx.x * 32, tid = threadIdx.x;
    int dl = tid & 31, k = tid >> 5;
    float acc = 0.f;
    for (int nc = 0; nc < 64; nc++) {
        int n0 = nc * 64;
#pragma unroll
        for (int i = 0; i < 8; i++) {
            int idx = tid + i * 256; int rr = idx >> 5, cc = idx & 31;
            vs[rr][cc] = g_vals[(size_t)(b * 4096 + n0 + rr) * 256 + d0 + cc];
        }
#pragma unroll
        for (int i = 0; i < 2; i++) {
            int p = tid + i * 256; int kk = p >> 6, nn = p & 63;
            as_[kk][nn] = attn[(size_t)(b * 8 + kk) * 4096 + n0 + nn];
        }
        __syncthreads();
#pragma unroll 8
        for (int nn = 0; nn < 64; nn++) acc += vs[nn][dl] * as_[k][nn];
        __syncthreads();
    }
    g_upd[(b * 8 + k) * 256 + d0 + dl] = acc / g_rowsum[b * 8 + k];
}

// ---------------- GRU cell + LN + residual MLP (block per batch) ------------
__global__ void __launch_bounds__(256) k_gru_mlp(
    const float* __restrict__ W_ih, const float* __restrict__ W_hh,
    const float* __restrict__ b_ih, const float* __restrict__ b_hh,
    const float* __restrict__ W1, const float* __restrict__ b1,
    const float* __restrict__ W2, const float* __restrict__ b2,
    const float* __restrict__ lg, const float* __restrict__ lb,
    float* __restrict__ out_final) {
    int b = blockIdx.x, tid = threadIdx.x, j = tid;
    __shared__ float u[8][256], h[8][256], snew[8][256], sn[8][256], ys[8][256];

    const float4* us = (const float4*)(g_upd + b * 8 * 256);
    const float4* hs = (const float4*)(g_slots + b * 8 * 256);
#pragma unroll
    for (int i = 0; i < 2; i++) {
        int p = tid + i * 256; int r = p >> 6, c4 = p & 63;
        *(float4*)&u[r][c4 * 4] = us[p];
        *(float4*)&h[r][c4 * 4] = hs[p];
    }
    __syncthreads();

    float rg[8], zg[8];
    // r gate (weight rows j)
    {
        float ai[8] = {}, ah[8] = {};
        const float4* wi = (const float4*)(W_ih + (size_t)j * 256);
        const float4* wh = (const float4*)(W_hh + (size_t)j * 256);
        for (int c4 = 0; c4 < 64; c4++) {
            float4 a = wi[c4], c = wh[c4];
#pragma unroll
            for (int r = 0; r < 8; r++) {
                float4 uu = *(float4*)&u[r][c4 * 4];
                float4 hh = *(float4*)&h[r][c4 * 4];
                ai[r] += a.x * uu.x + a.y * uu.y + a.z * uu.z + a.w * uu.w;
                ah[r] += c.x * hh.x + c.y * hh.y + c.z * hh.z + c.w * hh.w;
            }
        }
        float bi = b_ih[j], bh = b_hh[j];
#pragma unroll
        for (int r = 0; r < 8; r++) rg[r] = 1.f / (1.f + expf(-(ai[r] + bi + ah[r] + bh)));
    }
    // z gate (rows 256 + j)
    {
        float ai[8] = {}, ah[8] = {};
        const float4* wi = (const float4*)(W_ih + (size_t)(256 + j) * 256);
        const float4* wh = (const float4*)(W_hh + (size_t)(256 + j) * 256);
        for (int c4 = 0; c4 < 64; c4++) {
            float4 a = wi[c4], c = wh[c4];
#pragma unroll
            for (int r = 0; r < 8; r++) {
                float4 uu = *(float4*)&u[r][c4 * 4];
                float4 hh = *(float4*)&h[r][c4 * 4];
                ai[r] += a.x * uu.x + a.y * uu.y + a.z * uu.z + a.w * uu.w;
                ah[r] += c.x * hh.x + c.y * hh.y + c.z * hh.z + c.w * hh.w;
            }
        }
        float bi = b_ih[256 + j], bh = b_hh[256 + j];
#pragma unroll
        for (int r = 0; r < 8; r++) zg[r] = 1.f / (1.f + expf(-(ai[r] + bi + ah[r] + bh)));
    }
    // n gate (rows 512 + j) + combine
    {
        float ai[8] = {}, ah[8] = {};
        const float4* wi = (const float4*)(W_ih + (size_t)(512 + j) * 256);
        const float4* wh = (const float4*)(W_hh + (size_t)(512 + j) * 256);
        for (int c4 = 0; c4 < 64; c4++) {
            float4 a = wi[c4], c = wh[c4];
#pragma unroll
            for (int r = 0; r < 8; r++) {
                float4 uu = *(float4*)&u[r][c4 * 4];
                float4 hh = *(float4*)&h[r][c4 * 4];
                ai[r] += a.x * uu.x + a.y * uu.y + a.z * uu.z + a.w * uu.w;
                ah[r] += c.x * hh.x + c.y * hh.y + c.z * hh.z + c.w * hh.w;
            }
        }
        float bi = b_ih[512 + j], bh = b_hh[512 + j];
#pragma unroll
        for (int r = 0; r < 8; r++) {
            float n = tanhf(ai[r] + bi + rg[r] * (ah[r] + bh));
            snew[r][j] = (1.f - zg[r]) * n + zg[r] * h[r][j];
        }
    }
    __syncthreads();

    // LN(snew) -> sn  (warp per row)
    {
        int w = tid >> 5, lane = tid & 31;
        float4 v1 = *(float4*)&snew[w][lane * 4];
        float4 v2 = *(float4*)&snew[w][128 + lane * 4];
        float s = v1.x + v1.y + v1.z + v1.w + v2.x + v2.y + v2.z + v2.w;
        float ss = v1.x * v1.x + v1.y * v1.y + v1.z * v1.z + v1.w * v1.w
                 + v2.x * v2.x + v2.y * v2.y + v2.z * v2.z + v2.w * v2.w;
        wred2(s, ss);
        float m = s * (1.f / 256.f);
        float var = ss * (1.f / 256.f) - m * m;
        float rs = rsqrtf(var + 1e-5f);
        int d = lane * 4;
        sn[w][d + 0] = (v1.x - m) * rs * lg[d + 0] + lb[d + 0];
        sn[w][d + 1] = (v1.y - m) * rs * lg[d + 1] + lb[d + 1];
        sn[w][d + 2] = (v1.z - m) * rs * lg[d + 2] + lb[d + 2];
        sn[w][d + 3] = (v1.w - m) * rs * lg[d + 3] + lb[d + 3];
        int d2 = d + 128;
        sn[w][d2 + 0] = (v2.x - m) * rs * lg[d2 + 0] + lb[d2 + 0];
        sn[w][d2 + 1] = (v2.y - m) * rs * lg[d2 + 1] + lb[d2 + 1];
        sn[w][d2 + 2] = (v2.z - m) * rs * lg[d2 + 2] + lb[d2 + 2];
        sn[w][d2 + 3] = (v2.w - m) * rs * lg[d2 + 3] + lb[d2 + 3];
    }
    __syncthreads();

    // y = leaky_relu(sn @ W1^T + b1)
    {
        float acc[8] = {};
        const float4* w1 = (const float4*)(W1 + (size_t)j * 256);
        for (int c4 = 0; c4 < 64; c4++) {
            float4 a = w1[c4];
#pragma unroll
            for (int r = 0; r < 8; r++) {
                float4 s4 = *(float4*)&sn[r][c4 * 4];
                acc[r] += a.x * s4.x + a.y * s4.y + a.z * s4.z + a.w * s4.w;
            }
        }
        float bb = b1[j];
#pragma unroll
        for (int r = 0; r < 8; r++) {
            float t = acc[r] + bb;
            ys[r][j] = (t > 0.f) ? t : 0.01f * t;
        }
    }
    __syncthreads();

    // slots = snew + y @ W2^T + b2
    {
        float acc[8] = {};
        const float4* w2 = (const float4*)(W2 + (size_t)j * 256);
        for (int c4 = 0; c4 < 64; c4++) {
            float4 a = w2[c4];
#pragma unroll
            for (int r = 0; r < 8; r++) {
                float4 y4 = *(float4*)&ys[r][c4 * 4];
                acc[r] += a.x * y4.x + a.y * y4.y + a.z * y4.z + a.w * y4.w;
            }
        }
        float bb = b2[j];
#pragma unroll
        for (int r = 0; r < 8; r++) {
            float o = snew[r][j] + acc[r] + bb;
            g_slots[(b * 8 + r) * 256 + j] = o;
            if (out_final) out_final[(b * 8 + r) * 256 + j] = o;
        }
    }
}

// ---------------- launch ------------------------------------------------------
extern "C" void kernel_launch(void* const* d_in, const int* in_sizes, int n_in,
                              void* d_out, int out_size) {
    const float* emb   = (const float*)d_in[0];
    const float* noise = (const float*)d_in[1];
    const float* mu    = (const float*)d_in[2];
    const float* ls    = (const float*)d_in[3];
    const float* Wq    = (const float*)d_in[4];
    const float* Wk    = (const float*)d_in[5];
    const float* Wv    = (const float*)d_in[6];
    const float* W_ih  = (const float*)d_in[7];
    const float* W_hh  = (const float*)d_in[8];
    const float* b_ih  = (const float*)d_in[9];
    const float* b_hh  = (const float*)d_in[10];
    const float* W1    = (const float*)d_in[11];
    const float* b1    = (const float*)d_in[12];
    const float* W2    = (const float*)d_in[13];
    const float* b2    = (const float*)d_in[14];
    const float* lin_g = (const float*)d_in[15];
    const float* lin_b = (const float*)d_in[16];
    const float* lsl_g = (const float*)d_in[17];
    const float* lsl_b = (const float*)d_in[18];
    const float* lff_g = (const float*)d_in[19];
    const float* lff_b = (const float*)d_in[20];

    float* out       = (float*)d_out;
    float* out_slots = out;                      // [B,K,D]
    float* out_attn  = out + Bz * Kk * Dd;       // [B,K,N]

    // need the device-global attn scratch address for early iterations
    float* attn_scratch = nullptr;
    cudaGetSymbolAddress((void**)&attn_scratch, g_attn);

    // init slots
    k_init_slots<<<(Bz * Kk * Dd) / 256, 256>>>(noise, mu, ls);
    // LN row stats over embeddings
    k_rowstats<<<(Bz * Nn) / 8, 256>>>(emb);
    // keys / values
    k_dualgemm<<<dim3((Bz * Nn) / 64, 4), 256>>>(emb, Wk, Wv, lin_g, lin_b);

    for (int it = 0; it < 3; it++) {
        float* attn_buf = (it == 2) ? out_attn : attn_scratch;
        k_slots_q<<<Bz, 256>>>(lsl_g, lsl_b, Wq);
        k_dots<<<dim3(Nn / 32, Bz), 256>>>(attn_buf);
        k_updates<<<dim3(Dd / 32, Bz), 256>>>(attn_buf);
        k_gru_mlp<<<Bz, 256>>>(W_ih, W_hh, b_ih, b_hh, W1, b1, W2, b2,
                               lff_g, lff_b, (it == 2) ? out_slots : nullptr);
    }
}

// round 12
// speedup vs baseline: 2.3040x; 2.3040x over previous
#include <cuda_runtime.h>
#include <cstddef>

#define Bz 32
#define Nn 4096
#define Dd 256
#define Kk 8
#define NB 16              // n-chunks per batch in k_attn
#define NCH (Nn / NB)      // 256 rows per block

// ---------------- scratch (device globals; no allocations) -----------------
__device__ float g_slots[Bz * Kk * Dd];
__device__ float g_q[Bz * Kk * Dd];                       // q' = LN(slots)@Wq^T@Wk
__device__ float g_wqkT[Dd * Dd];                         // [f][e] = sum_d Wq[d,e]Wk[d,f]
__device__ float g_aggp[(size_t)NB * Bz * Kk * Dd];       // per-block partial agg
__device__ float g_rsp[NB * Bz * Kk];                     // per-block partial rowsum

__device__ __forceinline__ void wred2(float& a, float& b) {
#pragma unroll
    for (int o = 16; o > 0; o >>= 1) {
        a += __shfl_xor_sync(0xffffffffu, a, o);
        b += __shfl_xor_sync(0xffffffffu, b, o);
    }
}

// LN over one 256-row in smem, one warp per row (all 32 lanes call together)
__device__ __forceinline__ void ln_row(const float* __restrict__ in,
                                       float* __restrict__ out,
                                       const float* __restrict__ g,
                                       const float* __restrict__ bb, int lane) {
    float4 v1 = *(const float4*)(in + lane * 4);
    float4 v2 = *(const float4*)(in + 128 + lane * 4);
    float s = v1.x + v1.y + v1.z + v1.w + v2.x + v2.y + v2.z + v2.w;
    float ss = v1.x * v1.x + v1.y * v1.y + v1.z * v1.z + v1.w * v1.w
             + v2.x * v2.x + v2.y * v2.y + v2.z * v2.z + v2.w * v2.w;
    wred2(s, ss);
    float m = s * (1.f / 256.f);
    float rs = rsqrtf(ss * (1.f / 256.f) - m * m + 1e-5f);
    int d = lane * 4;
    float4 ga = *(const float4*)(g + d), ba = *(const float4*)(bb + d);
    out[d + 0] = (v1.x - m) * rs * ga.x + ba.x;
    out[d + 1] = (v1.y - m) * rs * ga.y + ba.y;
    out[d + 2] = (v1.z - m) * rs * ga.z + ba.z;
    out[d + 3] = (v1.w - m) * rs * ga.w + ba.w;
    int d2 = d + 128;
    float4 gb = *(const float4*)(g + d2), bbv = *(const float4*)(bb + d2);
    out[d2 + 0] = (v2.x - m) * rs * gb.x + bbv.x;
    out[d2 + 1] = (v2.y - m) * rs * gb.y + bbv.y;
    out[d2 + 2] = (v2.z - m) * rs * gb.z + bbv.z;
    out[d2 + 3] = (v2.w - m) * rs * gb.w + bbv.w;
}

// acc[r] += W[j,:] . src[r][:]  for 8 rows; src broadcast from smem
__device__ __forceinline__ void gemv8(const float* __restrict__ W, int j,
                                      const float (*src)[256], float acc[8]) {
    const float4* wr = (const float4*)(W + (size_t)j * 256);
#pragma unroll 4
    for (int c4 = 0; c4 < 64; c4++) {
        float4 w = wr[c4];
#pragma unroll
        for (int r = 0; r < 8; r++) {
            float4 s4 = *(const float4*)&src[r][c4 * 4];
            acc[r] += w.x * s4.x + w.y * s4.y + w.z * s4.z + w.w * s4.w;
        }
    }
}

__device__ __forceinline__ void gemv8_dual(const float* __restrict__ Wi,
                                           const float* __restrict__ Wh, int j,
                                           const float (*u)[256], const float (*h)[256],
                                           float ai[8], float ah[8]) {
    const float4* wi = (const float4*)(Wi + (size_t)j * 256);
    const float4* wh = (const float4*)(Wh + (size_t)j * 256);
#pragma unroll 2
    for (int c4 = 0; c4 < 64; c4++) {
        float4 a = wi[c4], c = wh[c4];
#pragma unroll
        for (int r = 0; r < 8; r++) {
            float4 uu = *(const float4*)&u[r][c4 * 4];
            float4 hh = *(const float4*)&h[r][c4 * 4];
            ai[r] += a.x * uu.x + a.y * uu.y + a.z * uu.z + a.w * uu.w;
            ah[r] += c.x * hh.x + c.y * hh.y + c.z * hh.z + c.w * hh.w;
        }
    }
}

// ---------------- slot init -------------------------------------------------
__global__ void k_init_slots(const float* __restrict__ noise,
                             const float* __restrict__ mu,
                             const float* __restrict__ ls) {
    int i = blockIdx.x * 256 + threadIdx.x;
    int d = i & 255;
    g_slots[i] = mu[d] + expf(ls[d]) * noise[i];
}

// ---------------- Wqk^T[f][e] = sum_d Wq[d,e] * Wk[d,f] (once) --------------
__global__ void __launch_bounds__(256) k_wqk(const float* __restrict__ Wq,
                                             const float* __restrict__ Wk) {
    __shared__ float sq[32][33], sk[32][33];
    int be = blockIdx.x, bf = blockIdx.y, tid = threadIdx.x;
    int dd = tid >> 3, e4 = (tid & 7) * 4;
    int ff = tid & 31, eo = (tid >> 5) * 4;
    float acc[4] = {};
    for (int d0 = 0; d0 < 256; d0 += 32) {
        float4 q4 = *(const float4*)(Wq + (size_t)(d0 + dd) * 256 + be * 32 + e4);
        float4 k4 = *(const float4*)(Wk + (size_t)(d0 + dd) * 256 + bf * 32 + e4);
        sq[dd][e4 + 0] = q4.x; sq[dd][e4 + 1] = q4.y; sq[dd][e4 + 2] = q4.z; sq[dd][e4 + 3] = q4.w;
        sk[dd][e4 + 0] = k4.x; sk[dd][e4 + 1] = k4.y; sk[dd][e4 + 2] = k4.z; sk[dd][e4 + 3] = k4.w;
        __syncthreads();
#pragma unroll
        for (int d = 0; d < 32; d++) {
            float kv = sk[d][ff];
            acc[0] += sq[d][eo + 0] * kv;
            acc[1] += sq[d][eo + 1] * kv;
            acc[2] += sq[d][eo + 2] * kv;
            acc[3] += sq[d][eo + 3] * kv;
        }
        __syncthreads();
    }
    float* o = g_wqkT + (size_t)(bf * 32 + ff) * 256 + be * 32 + eo;
    o[0] = acc[0]; o[1] = acc[1]; o[2] = acc[2]; o[3] = acc[3];
}

// ---------------- prep for iteration 0: q' = LN(slots) @ WqkT^T -------------
__global__ void __launch_bounds__(256) k_prep0(const float* __restrict__ lslg,
                                               const float* __restrict__ lslb) {
    int b = blockIdx.x, tid = threadIdx.x, warp = tid >> 5, lane = tid & 31;
    __shared__ __align__(16) float h[8][256], sn[8][256];
#pragma unroll
    for (int i = 0; i < 8; i++) {
        int elem = i * 256 + tid; int r = elem >> 8, e = elem & 255;
        h[r][e] = g_slots[(b * 8 + r) * 256 + e];
    }
    __syncthreads();
    ln_row(&h[warp][0], &sn[warp][0], lslg, lslb, lane);
    __syncthreads();
    float acc[8] = {};
    gemv8(g_wqkT, tid, sn, acc);
#pragma unroll
    for (int r = 0; r < 8; r++) g_q[(b * 8 + r) * 256 + tid] = acc[r];
}

// ---------------- fused attention pass over emb ----------------------------
// per block: 256 n rows; LN(emb) inline; dots = q'.x̂; softmax over 8 slots;
// accumulate rowsum and agg = attn @ x̂ (partials per block; no atomics)
__global__ void __launch_bounds__(256) k_attn(const float* __restrict__ emb,
                                              const float* __restrict__ lg,
                                              const float* __restrict__ lb,
                                              float* __restrict__ attn_out) {
    __shared__ __align__(16) float qs[8][260];
    __shared__ __align__(16) float xt[32][260];
    __shared__ __align__(16) float at4[32][8];
    __shared__ float rs_s[8][33];
    int b = blockIdx.y, nb = blockIdx.x, tid = threadIdx.x;
    int warp = tid >> 5, lane = tid & 31;
    int kk = tid & 7, nl = tid >> 3;

    // load q' for this batch
    {
        const float4* qsrc = (const float4*)(g_q + b * 8 * 256);
#pragma unroll
        for (int i = 0; i < 2; i++) {
            int p = tid + i * 256; int r = p >> 6, c4 = p & 63;
            *(float4*)&qs[r][c4 * 4] = qsrc[p];
        }
    }
    // LN params for this lane's 8 columns
    float4 gA = *(const float4*)(lg + lane * 4);
    float4 gB = *(const float4*)(lg + 128 + lane * 4);
    float4 bA = *(const float4*)(lb + lane * 4);
    float4 bB = *(const float4*)(lb + 128 + lane * 4);

    float aggr[8] = {};
    float rsl = 0.f;

    for (int t8 = 0; t8 < 8; t8++) {
        int n0 = nb * NCH + t8 * 32;
        // stage: each warp LNs 4 rows into xt
#pragma unroll
        for (int rr = 0; rr < 4; rr++) {
            int row = warp * 4 + rr;
            const float* er = emb + ((size_t)b * Nn + n0 + row) * 256;
            float4 v1 = *(const float4*)(er + lane * 4);
            float4 v2 = *(const float4*)(er + 128 + lane * 4);
            float s = v1.x + v1.y + v1.z + v1.w + v2.x + v2.y + v2.z + v2.w;
            float ss = v1.x * v1.x + v1.y * v1.y + v1.z * v1.z + v1.w * v1.w
                     + v2.x * v2.x + v2.y * v2.y + v2.z * v2.z + v2.w * v2.w;
            wred2(s, ss);
            float m = s * (1.f / 256.f);
            float rs = rsqrtf(ss * (1.f / 256.f) - m * m + 1e-5f);
            int d = lane * 4;
            xt[row][d + 0] = (v1.x - m) * rs * gA.x + bA.x;
            xt[row][d + 1] = (v1.y - m) * rs * gA.y + bA.y;
            xt[row][d + 2] = (v1.z - m) * rs * gA.z + bA.z;
            xt[row][d + 3] = (v1.w - m) * rs * gA.w + bA.w;
            int d2 = d + 128;
            xt[row][d2 + 0] = (v2.x - m) * rs * gB.x + bB.x;
            xt[row][d2 + 1] = (v2.y - m) * rs * gB.y + bB.y;
            xt[row][d2 + 2] = (v2.z - m) * rs * gB.z + bB.z;
            xt[row][d2 + 3] = (v2.w - m) * rs * gB.w + bB.w;
        }
        __syncthreads();

        // dots: thread (kk, nl)
        float acc = 0.f;
#pragma unroll 8
        for (int c4 = 0; c4 < 64; c4++) {
            float4 q4 = *(const float4*)&qs[kk][c4 * 4];
            float4 x4 = *(const float4*)&xt[nl][c4 * 4];
            acc += q4.x * x4.x + q4.y * x4.y + q4.z * x4.z + q4.w * x4.w;
        }
        acc *= 0.0625f;
        // softmax over 8 slots (lanes xor 1,2,4)
        float mx = acc;
        mx = fmaxf(mx, __shfl_xor_sync(0xffffffffu, mx, 1));
        mx = fmaxf(mx, __shfl_xor_sync(0xffffffffu, mx, 2));
        mx = fmaxf(mx, __shfl_xor_sync(0xffffffffu, mx, 4));
        float ev = expf(acc - mx);
        float sm = ev;
        sm += __shfl_xor_sync(0xffffffffu, sm, 1);
        sm += __shfl_xor_sync(0xffffffffu, sm, 2);
        sm += __shfl_xor_sync(0xffffffffu, sm, 4);
        float a = ev / sm + 1e-8f;
        rsl += a;
        at4[nl][kk] = a;
        __syncthreads();

        // optional attn_vis store (coalesced)
        if (attn_out) {
            int k2 = tid >> 5, n2 = tid & 31;
            attn_out[(size_t)(b * 8 + k2) * Nn + n0 + n2] = at4[n2][k2];
        }
        // agg accumulation: thread owns column e = tid for all 8 slots
        int e = tid;
#pragma unroll 8
        for (int n = 0; n < 32; n++) {
            float xv = xt[n][e];
            float4 a0 = *(const float4*)&at4[n][0];
            float4 a1 = *(const float4*)&at4[n][4];
            aggr[0] += a0.x * xv; aggr[1] += a0.y * xv;
            aggr[2] += a0.z * xv; aggr[3] += a0.w * xv;
            aggr[4] += a1.x * xv; aggr[5] += a1.y * xv;
            aggr[6] += a1.z * xv; aggr[7] += a1.w * xv;
        }
        __syncthreads();
    }

    // deterministic rowsum reduce
    rs_s[kk][nl] = rsl;
    __syncthreads();
    if (tid < 8) {
        float s = 0.f;
#pragma unroll
        for (int i = 0; i < 32; i++) s += rs_s[tid][i];
        g_rsp[(nb * Bz + b) * 8 + tid] = s;
    }
    size_t base = (size_t)(nb * Bz + b) * 8 * 256;
#pragma unroll
    for (int k = 0; k < 8; k++) g_aggp[base + k * 256 + tid] = aggr[k];
}

// ---------------- fused: upd -> GRU -> LN -> MLP -> (next q') ---------------
__global__ void __launch_bounds__(256) k_fused(
    const float* __restrict__ Wv,
    const float* __restrict__ W_ih, const float* __restrict__ W_hh,
    const float* __restrict__ b_ih, const float* __restrict__ b_hh,
    const float* __restrict__ W1, const float* __restrict__ b1,
    const float* __restrict__ W2, const float* __restrict__ b2,
    const float* __restrict__ lffg, const float* __restrict__ lffb,
    const float* __restrict__ lslg, const float* __restrict__ lslb,
    float* __restrict__ out_slots, int do_prep) {
    int b = blockIdx.x, tid = threadIdx.x, j = tid;
    int warp = tid >> 5, lane = tid & 31;
    __shared__ __align__(16) float ag[8][256], h[8][256], us[8][256], snew[8][256], sn[8][256];
    __shared__ float rinv[8];

    // reduce agg partials (fixed order -> deterministic), load slots
#pragma unroll
    for (int i = 0; i < 8; i++) {
        int elem = i * 256 + tid; int r = elem >> 8, e = elem & 255;
        float a = 0.f;
#pragma unroll
        for (int nb = 0; nb < NB; nb++) a += g_aggp[((size_t)(nb * Bz + b) * 8 + r) * 256 + e];
        ag[r][e] = a;
        h[r][e] = g_slots[(b * 8 + r) * 256 + e];
    }
    if (tid < 8) {
        float s = 0.f;
#pragma unroll
        for (int nb = 0; nb < NB; nb++) s += g_rsp[(nb * Bz + b) * 8 + tid];
        rinv[tid] = 1.f / s;
    }
    __syncthreads();

    // updates = (agg/rowsum) @ Wv^T
    {
        float acc[8] = {};
        gemv8(Wv, j, ag, acc);
#pragma unroll
        for (int r = 0; r < 8; r++) us[r][j] = acc[r] * rinv[r];
    }
    __syncthreads();

    // GRU gates
    float rg[8], zg[8];
    {
        float ai[8] = {}, ah[8] = {};
        gemv8_dual(W_ih, W_hh, j, us, h, ai, ah);
        float bi = b_ih[j], bh = b_hh[j];
#pragma unroll
        for (int r = 0; r < 8; r++) rg[r] = 1.f / (1.f + expf(-(ai[r] + bi + ah[r] + bh)));
    }
    {
        float ai[8] = {}, ah[8] = {};
        gemv8_dual(W_ih + (size_t)256 * 256, W_hh + (size_t)256 * 256, j, us, h, ai, ah);
        float bi = b_ih[256 + j], bh = b_hh[256 + j];
#pragma unroll
        for (int r = 0; r < 8; r++) zg[r] = 1.f / (1.f + expf(-(ai[r] + bi + ah[r] + bh)));
    }
    {
        float ai[8] = {}, ah[8] = {};
        gemv8_dual(W_ih + (size_t)512 * 256, W_hh + (size_t)512 * 256, j, us, h, ai, ah);
        float bi = b_ih[512 + j], bh = b_hh[512 + j];
#pragma unroll
        for (int r = 0; r < 8; r++) {
            float n = tanhf(ai[r] + bi + rg[r] * (ah[r] + bh));
            snew[r][j] = (1.f - zg[r]) * n + zg[r] * h[r][j];
        }
    }
    __syncthreads();

    // LN(snew) -> sn
    ln_row(&snew[warp][0], &sn[warp][0], lffg, lffb, lane);
    __syncthreads();

    // mlp1 -> ag (alias ys)
    {
        float acc[8] = {};
        gemv8(W1, j, sn, acc);
        float bb = b1[j];
#pragma unroll
        for (int r = 0; r < 8; r++) {
            float t = acc[r] + bb;
            ag[r][j] = (t > 0.f) ? t : 0.01f * t;
        }
    }
    __syncthreads();

    // mlp2 + residual
    {
        float acc[8] = {};
        gemv8(W2, j, ag, acc);
        float bb = b2[j];
#pragma unroll
        for (int r = 0; r < 8; r++) {
            float o = snew[r][j] + acc[r] + bb;
            g_slots[(b * 8 + r) * 256 + j] = o;
            if (out_slots) out_slots[(b * 8 + r) * 256 + j] = o;
            h[r][j] = o;
        }
    }
    __syncthreads();

    // next-iteration prep: q' = LN(slots) @ WqkT^T
    if (do_prep) {
        ln_row(&h[warp][0], &sn[warp][0], lslg, lslb, lane);
        __syncthreads();
        float acc[8] = {};
        gemv8(g_wqkT, j, sn, acc);
#pragma unroll
        for (int r = 0; r < 8; r++) g_q[(b * 8 + r) * 256 + j] = acc[r];
    }
}

// ---------------- launch -----------------------------------------------------
extern "C" void kernel_launch(void* const* d_in, const int* in_sizes, int n_in,
                              void* d_out, int out_size) {
    const float* emb   = (const float*)d_in[0];
    const float* noise = (const float*)d_in[1];
    const float* mu    = (const float*)d_in[2];
    const float* ls    = (const float*)d_in[3];
    const float* Wq    = (const float*)d_in[4];
    const float* Wk    = (const float*)d_in[5];
    const float* Wv    = (const float*)d_in[6];
    const float* W_ih  = (const float*)d_in[7];
    const float* W_hh  = (const float*)d_in[8];
    const float* b_ih  = (const float*)d_in[9];
    const float* b_hh  = (const float*)d_in[10];
    const float* W1    = (const float*)d_in[11];
    const float* b1    = (const float*)d_in[12];
    const float* W2    = (const float*)d_in[13];
    const float* b2    = (const float*)d_in[14];
    const float* lin_g = (const float*)d_in[15];
    const float* lin_b = (const float*)d_in[16];
    const float* lsl_g = (const float*)d_in[17];
    const float* lsl_b = (const float*)d_in[18];
    const float* lff_g = (const float*)d_in[19];
    const float* lff_b = (const float*)d_in[20];

    float* out       = (float*)d_out;
    float* out_slots = out;                  // [B,K,D]
    float* out_attn  = out + Bz * Kk * Dd;   // [B,K,N]

    k_init_slots<<<(Bz * Kk * Dd) / 256, 256>>>(noise, mu, ls);
    k_wqk<<<dim3(8, 8), 256>>>(Wq, Wk);
    k_prep0<<<Bz, 256>>>(lsl_g, lsl_b);

    for (int it = 0; it < 3; it++) {
        k_attn<<<dim3(NB, Bz), 256>>>(emb, lin_g, lin_b,
                                      (it == 2) ? out_attn : nullptr);
        k_fused<<<Bz, 256>>>(Wv, W_ih, W_hh, b_ih, b_hh, W1, b1, W2, b2,
                             lff_g, lff_b, lsl_g, lsl_b,
                             (it == 2) ? out_slots : nullptr,
                             (it < 2) ? 1 : 0);
    }
}